// round 16
// baseline (speedup 1.0000x reference)
#include <cuda_runtime.h>
#include <cuda_bf16.h>
#include <math.h>

// Problem constants
#define BB    128
#define TT    512
#define FF    256
#define HH    1024
#define GST   512
#define ITR   512
#define KGC   1280      // gate/cand reduction dim

// Launch shape: 64 fat CTAs, 32 warps each (4 warps cooperate per batch mtile)
#define NCTAS 64
#define NTHR  1024

// ---------------- device globals (scratch + barrier state) ----------------
__device__ unsigned g_bar_count = 0;
__device__ unsigned g_bar_sense = 0;

// Fragment-ready split-bf16 scratches. u32 = 2 bf16 (k, k+1 halves).
// X: [t][mt 8][kt 16][lane 32][reg 4]
__device__ __align__(16) unsigned g_Xh[(size_t)TT * 8 * 16 * 32 * 4];
__device__ __align__(16) unsigned g_Xl[(size_t)TT * 8 * 16 * 32 * 4];
// H ping-pong: [buf 2][mt 8][kt 64][lane][reg]   (h = [ghost | intr], k=1024)
__device__ __align__(16) unsigned g_Hh[2 * 8 * 64 * 32 * 4];
__device__ __align__(16) unsigned g_Hl[2 * 8 * 64 * 32 * 4];
// R (r*h_intr): [mt 8][kt 32][lane][reg]
__device__ __align__(16) unsigned g_Rh[8 * 32 * 32 * 4];
__device__ __align__(16) unsigned g_Rl[8 * 32 * 32 * 4];
// elementwise fp32 scratch
__device__ __align__(16) float g_u[BB * ITR];        // u gate [b][n]
__device__ __align__(16) float g_hf[2][BB * HH];     // fp32 h ping-pong

// Grid-wide sense-reversing barrier (64 CTAs, 1/SM, single wave).
// 1536 barriers/launch (even) -> sense ends 0; count wraps -> replay-safe.
__device__ __forceinline__ void grid_barrier(unsigned sense) {
    __syncthreads();
    if (threadIdx.x == 0) {
        __threadfence();
        unsigned old = atomicInc(&g_bar_count, NCTAS - 1u);
        if (old == NCTAS - 1u) {
            atomicExch(&g_bar_sense, sense);
        } else {
            while (((volatile unsigned*)&g_bar_sense)[0] != sense) { }
        }
        __threadfence();
    }
    __syncthreads();
}

// ---------------- bf16-split helpers ----------------
__device__ __forceinline__ unsigned bfpack(float v0, float v1) {
    unsigned short s0 = __bfloat16_as_ushort(__float2bfloat16(v0));
    unsigned short s1 = __bfloat16_as_ushort(__float2bfloat16(v1));
    return (unsigned)s0 | ((unsigned)s1 << 16);
}
__device__ __forceinline__ float bflo(float v) {
    return v - __bfloat162float(__float2bfloat16(v));
}

// mma.sync m16n8k16 row.col bf16 -> f32
__device__ __forceinline__ void mma_bf16(float* c, uint4 a, unsigned b0, unsigned b1) {
    asm volatile(
        "mma.sync.aligned.m16n8k16.row.col.f32.bf16.bf16.f32 "
        "{%0,%1,%2,%3},{%4,%5,%6,%7},{%8,%9},{%0,%1,%2,%3};"
        : "+f"(c[0]), "+f"(c[1]), "+f"(c[2]), "+f"(c[3])
        : "r"(a.x), "r"(a.y), "r"(a.z), "r"(a.w), "r"(b0), "r"(b1));
}

struct Frag3 { float hh[4], hl[4], lh[4]; };
__device__ __forceinline__ void f3zero(Frag3& f) {
    #pragma unroll
    for (int i = 0; i < 4; ++i) { f.hh[i] = 0.f; f.hl[i] = 0.f; f.lh[i] = 0.f; }
}
// 3-term split accumulation: C += Ah*Bh + Ah*Bl + Al*Bh (independent accs)
__device__ __forceinline__ void mma3(Frag3& f, uint4 Ah, uint4 Al, uint2 Bh, uint2 Bl) {
    mma_bf16(f.hh, Ah, Bh.x, Bh.y);
    mma_bf16(f.hl, Ah, Bl.x, Bl.y);
    mma_bf16(f.lh, Al, Bh.x, Bh.y);
}
__device__ __forceinline__ float f3get(const Frag3& f, int i) {
    return f.hh[i] + f.hl[i] + f.lh[i];
}

// A-fragment u32 index math (value pair at batch-row m, even k-col k0)
__device__ __forceinline__ int frag_idx(int m, int k0) {
    int rr = m & 15, kk = k0 & 15;
    return ((rr & 7) * 4 + ((kk & 7) >> 1)) * 4 + (rr >> 3) + ((kk >> 3) << 1);
}

// ---------------- pre-pass: split x (all t) and h0 into fragment scratch ----------------
extern "C" __global__ void gg_pack(const float* __restrict__ x,
                                   const float* __restrict__ hid) {
    const size_t nX = (size_t)TT * 8 * 16 * 32 * 4;
    for (size_t i = (size_t)blockIdx.x * blockDim.x + threadIdx.x; i < nX;
         i += (size_t)gridDim.x * blockDim.x) {
        unsigned reg = (unsigned)i & 3u;
        unsigned lane = (unsigned)(i >> 2) & 31u;
        unsigned kt = (unsigned)(i >> 7) & 15u;
        unsigned mt = (unsigned)(i >> 11) & 7u;
        unsigned t  = (unsigned)(i >> 14);
        int r  = (int)(lane >> 2) + (int)(reg & 1u) * 8;
        int k0 = (int)kt * 16 + (int)(lane & 3u) * 2 + (int)(reg >> 1) * 8;
        int b  = (int)mt * 16 + r;
        float v0 = x[((size_t)b * TT + t) * FF + k0];
        float v1 = x[((size_t)b * TT + t) * FF + k0 + 1];
        g_Xh[i] = bfpack(v0, v1);
        g_Xl[i] = bfpack(bflo(v0), bflo(v1));
    }
    const int nH = 8 * 64 * 32 * 4;     // buf 0 only
    for (int i = blockIdx.x * blockDim.x + threadIdx.x; i < nH;
         i += gridDim.x * blockDim.x) {
        int reg = i & 3, lane = (i >> 2) & 31, kt = (i >> 7) & 63, mt = (i >> 13) & 7;
        int r  = (lane >> 2) + (reg & 1) * 8;
        int k0 = kt * 16 + (lane & 3) * 2 + (reg >> 1) * 8;
        int b  = mt * 16 + r;
        float v0 = hid[b * HH + k0], v1 = hid[b * HH + k0 + 1];
        g_Hh[i] = bfpack(v0, v1);
        g_Hl[i] = bfpack(bflo(v0), bflo(v1));
    }
    for (int i = blockIdx.x * blockDim.x + threadIdx.x; i < BB * HH;
         i += gridDim.x * blockDim.x)
        g_hf[0][i] = hid[i];
}

// ---------------- persistent tensor-core kernel ----------------
extern "C" __global__ void __launch_bounds__(NTHR, 1)
ghostgru_tc(const float* __restrict__ Wg,    // (1024, 1280)
            const float* __restrict__ Wc,    // (512, 1280)
            const float* __restrict__ Wh,    // (512, 512)
            const float* __restrict__ bg,
            const float* __restrict__ bc,
            const float* __restrict__ bh,
            float*       __restrict__ out,   // (B,T,H) [+ (B,H) tail]
            int out_size)
{
    extern __shared__ unsigned smu[];
    unsigned* sWgh = smu;                  // gate B frags hi: [nt2][kt80][lane][reg2]
    unsigned* sWgl = sWgh + 2 * 80 * 64;   // 10240 each
    unsigned* sWch = sWgl + 2 * 80 * 64;   // cand: [kt80][lane][reg2] = 5120
    unsigned* sWcl = sWch + 80 * 64;
    unsigned* sWhh = sWcl + 80 * 64;       // ghost: [kt32][lane][reg2] = 2048
    unsigned* sWhl = sWhh + 32 * 64;
    float* sBg = (float*)(sWhl + 32 * 64); // 16
    float* sBc = sBg + 16;                 // 8
    float* sBh = sBc + 8;                  // 8
    float4* sPart = (float4*)(sBh + 8);    // [32 warps][32 lanes] partial C = 16KB

    const int cta  = blockIdx.x;
    const int tid  = threadIdx.x;
    const int w    = tid >> 5;             // warp 0..31
    const int w4   = w >> 2;               // batch mtile 0..7
    const int q    = w & 3;                // role within 4-warp team
    const int lane = tid & 31;
    const bool is_r = (cta < 32);          // gate rows < 512 are r-gates

    // ---- stage split weights into SMEM in B-fragment order ----
    for (int p = tid; p < 2 * 80 * 64; p += NTHR) {
        int nt = p / (80 * 64); int rem = p % (80 * 64);
        int kt = rem >> 6; int qq = rem & 63; int ln = qq >> 1; int rg = qq & 1;
        int nrow = cta * 16 + nt * 8 + (ln >> 2);
        int k0 = kt * 16 + (ln & 3) * 2 + rg * 8;
        float v0 = Wg[(size_t)nrow * KGC + k0];
        float v1 = Wg[(size_t)nrow * KGC + k0 + 1];
        sWgh[p] = bfpack(v0, v1);
        sWgl[p] = bfpack(bflo(v0), bflo(v1));
    }
    for (int p = tid; p < 80 * 64; p += NTHR) {
        int kt = p >> 6; int qq = p & 63; int ln = qq >> 1; int rg = qq & 1;
        int nrow = cta * 8 + (ln >> 2);
        int k0 = kt * 16 + (ln & 3) * 2 + rg * 8;
        float v0 = Wc[(size_t)nrow * KGC + k0];
        float v1 = Wc[(size_t)nrow * KGC + k0 + 1];
        sWch[p] = bfpack(v0, v1);
        sWcl[p] = bfpack(bflo(v0), bflo(v1));
    }
    for (int p = tid; p < 32 * 64; p += NTHR) {
        int kt = p >> 6; int qq = p & 63; int ln = qq >> 1; int rg = qq & 1;
        int nrow = cta * 8 + (ln >> 2);
        int k0 = kt * 16 + (ln & 3) * 2 + rg * 8;
        float v0 = Wh[(size_t)nrow * ITR + k0];
        float v1 = Wh[(size_t)nrow * ITR + k0 + 1];
        sWhh[p] = bfpack(v0, v1);
        sWhl[p] = bfpack(bflo(v0), bflo(v1));
    }
    if (tid < 16) sBg[tid] = bg[cta * 16 + tid];
    if (tid < 8)  sBc[tid] = bc[cta * 8 + tid];
    if (tid < 8)  sBh[tid] = bh[cta * 8 + tid];
    __syncthreads();

    const uint2* Bg_h = (const uint2*)sWgh;   // index (nt*80+kt)*32 + lane
    const uint2* Bg_l = (const uint2*)sWgl;
    const uint2* Bc_h = (const uint2*)sWch;   // index kt*32 + lane
    const uint2* Bc_l = (const uint2*)sWcl;
    const uint2* Bh_h = (const uint2*)sWhh;
    const uint2* Bh_l = (const uint2*)sWhl;

    unsigned sense = 0;

    for (int t = 0; t < TT; ++t) {
        const int buf = t & 1, nbuf = (t + 1) & 1;
        const float* hfo = g_hf[buf];
        float*       hfn = g_hf[nbuf];

        const uint4* Xh4 = ((const uint4*)g_Xh) + (((size_t)t * 8 + w4) * 16) * 32 + lane;
        const uint4* Xl4 = ((const uint4*)g_Xl) + (((size_t)t * 8 + w4) * 16) * 32 + lane;
        const uint4* Hh4 = ((const uint4*)g_Hh) + ((buf * 8 + w4) * 64) * 32 + lane;
        const uint4* Hl4 = ((const uint4*)g_Hl) + ((buf * 8 + w4) * 64) * 32 + lane;
        const uint4* Rh4 = ((const uint4*)g_Rh) + (w4 * 32) * 32 + lane;
        const uint4* Rl4 = ((const uint4*)g_Rl) + (w4 * 32) * 32 + lane;

        // ====== phase 1: gate. Team of 4: (ntile = q&1, k-half = q>>1), 40 kt each ======
        {
            Frag3 F; f3zero(F);
            const int nt  = q & 1;
            const int kh  = q >> 1;
            const int ntb = nt * 80;
            if (kh == 0) {
                #pragma unroll 4
                for (int kt = 0; kt < 16; ++kt) {       // x: logical 0..15
                    uint4 Ah = __ldg(Xh4 + kt * 32);
                    uint4 Al = __ldg(Xl4 + kt * 32);
                    uint2 bhv = Bg_h[(ntb + kt) * 32 + lane];
                    uint2 blv = Bg_l[(ntb + kt) * 32 + lane];
                    mma3(F, Ah, Al, bhv, blv);
                }
                #pragma unroll 4
                for (int kt = 0; kt < 24; ++kt) {       // h: logical 16..39
                    uint4 Ah = __ldcg(Hh4 + kt * 32);
                    uint4 Al = __ldcg(Hl4 + kt * 32);
                    uint2 bhv = Bg_h[(ntb + 16 + kt) * 32 + lane];
                    uint2 blv = Bg_l[(ntb + 16 + kt) * 32 + lane];
                    mma3(F, Ah, Al, bhv, blv);
                }
            } else {
                #pragma unroll 4
                for (int kt = 24; kt < 64; ++kt) {      // h: logical 40..79
                    uint4 Ah = __ldcg(Hh4 + kt * 32);
                    uint4 Al = __ldcg(Hl4 + kt * 32);
                    uint2 bhv = Bg_h[(ntb + 16 + kt) * 32 + lane];
                    uint2 blv = Bg_l[(ntb + 16 + kt) * 32 + lane];
                    mma3(F, Ah, Al, bhv, blv);
                }
            }
            sPart[w * 32 + lane] = make_float4(f3get(F, 0), f3get(F, 1),
                                               f3get(F, 2), f3get(F, 3));
            __syncthreads();
            if (q < 2) {                                // q = nt (kh=0 warps)
                float4 pa = sPart[(w4 * 4 + q) * 32 + lane];
                float4 pb = sPart[(w4 * 4 + q + 2) * 32 + lane];
                float c0 = pa.x + pb.x, c1 = pa.y + pb.y;
                float c2 = pa.z + pb.z, c3 = pa.w + pb.w;
                int nl0 = q * 8 + 2 * (lane & 3);
                int ng0 = cta * 16 + nl0;               // gate row (even)
                float bia0 = sBg[nl0], bia1 = sBg[nl0 + 1];
                #pragma unroll
                for (int rh = 0; rh < 2; ++rh) {
                    int b = w4 * 16 + (lane >> 2) + rh * 8;
                    float z0 = (rh ? c2 : c0) + bia0;
                    float z1 = (rh ? c3 : c1) + bia1;
                    float s0 = 1.0f / (1.0f + __expf(-z0));
                    float s1 = 1.0f / (1.0f + __expf(-z1));
                    if (is_r) {
                        float2 ho = __ldcg((const float2*)&hfo[b * HH + GST + ng0]);
                        float r0 = s0 * ho.x, r1 = s1 * ho.y;
                        int idx = ((w4 * 32 + (ng0 >> 4)) * 32) * 4 + frag_idx(b, ng0);
                        g_Rh[idx] = bfpack(r0, r1);
                        g_Rl[idx] = bfpack(bflo(r0), bflo(r1));
                    } else {
                        *(float2*)&g_u[b * ITR + (ng0 - GST)] = make_float2(s0, s1);
                    }
                }
            }
        }
        sense ^= 1u; grid_barrier(sense);

        // ====== phase 2: cand. Team of 4 splits k 20/20/20/20 ======
        {
            Frag3 F; f3zero(F);
            if (q == 0) {
                #pragma unroll 4
                for (int kt = 0; kt < 16; ++kt) {       // x: logical 0..15
                    uint4 Ah = __ldg(Xh4 + kt * 32);
                    uint4 Al = __ldg(Xl4 + kt * 32);
                    uint2 bhv = Bc_h[kt * 32 + lane], blv = Bc_l[kt * 32 + lane];
                    mma3(F, Ah, Al, bhv, blv);
                }
                #pragma unroll 4
                for (int kt = 0; kt < 4; ++kt) {        // ghost: logical 16..19
                    uint4 Ah = __ldcg(Hh4 + kt * 32);
                    uint4 Al = __ldcg(Hl4 + kt * 32);
                    uint2 bhv = Bc_h[(16 + kt) * 32 + lane];
                    uint2 blv = Bc_l[(16 + kt) * 32 + lane];
                    mma3(F, Ah, Al, bhv, blv);
                }
            } else if (q == 1) {
                #pragma unroll 4
                for (int kt = 4; kt < 24; ++kt) {       // ghost: logical 20..39
                    uint4 Ah = __ldcg(Hh4 + kt * 32);
                    uint4 Al = __ldcg(Hl4 + kt * 32);
                    uint2 bhv = Bc_h[(16 + kt) * 32 + lane];
                    uint2 blv = Bc_l[(16 + kt) * 32 + lane];
                    mma3(F, Ah, Al, bhv, blv);
                }
            } else if (q == 2) {
                #pragma unroll 4
                for (int kt = 24; kt < 32; ++kt) {      // ghost: logical 40..47
                    uint4 Ah = __ldcg(Hh4 + kt * 32);
                    uint4 Al = __ldcg(Hl4 + kt * 32);
                    uint2 bhv = Bc_h[(16 + kt) * 32 + lane];
                    uint2 blv = Bc_l[(16 + kt) * 32 + lane];
                    mma3(F, Ah, Al, bhv, blv);
                }
                #pragma unroll 4
                for (int kt = 0; kt < 12; ++kt) {       // r: logical 48..59
                    uint4 Ah = __ldcg(Rh4 + kt * 32);
                    uint4 Al = __ldcg(Rl4 + kt * 32);
                    uint2 bhv = Bc_h[(48 + kt) * 32 + lane];
                    uint2 blv = Bc_l[(48 + kt) * 32 + lane];
                    mma3(F, Ah, Al, bhv, blv);
                }
            } else {
                #pragma unroll 4
                for (int kt = 12; kt < 32; ++kt) {      // r: logical 60..79
                    uint4 Ah = __ldcg(Rh4 + kt * 32);
                    uint4 Al = __ldcg(Rl4 + kt * 32);
                    uint2 bhv = Bc_h[(48 + kt) * 32 + lane];
                    uint2 blv = Bc_l[(48 + kt) * 32 + lane];
                    mma3(F, Ah, Al, bhv, blv);
                }
            }
            sPart[w * 32 + lane] = make_float4(f3get(F, 0), f3get(F, 1),
                                               f3get(F, 2), f3get(F, 3));
            __syncthreads();
            if (q < 2) {                                // q = row-half rh
                float4 p0 = sPart[(w4 * 4 + 0) * 32 + lane];
                float4 p1 = sPart[(w4 * 4 + 1) * 32 + lane];
                float4 p2 = sPart[(w4 * 4 + 2) * 32 + lane];
                float4 p3 = sPart[(w4 * 4 + 3) * 32 + lane];
                float c0v = q ? (p0.z + p1.z + p2.z + p3.z)
                              : (p0.x + p1.x + p2.x + p3.x);
                float c1v = q ? (p0.w + p1.w + p2.w + p3.w)
                              : (p0.y + p1.y + p2.y + p3.y);
                int nl0 = 2 * (lane & 3);
                int n0  = cta * 8 + nl0;                // intr col (even)
                float c0 = tanhf(c0v + sBc[nl0]);
                float c1 = tanhf(c1v + sBc[nl0 + 1]);
                int b = w4 * 16 + (lane >> 2) + q * 8;
                float2 uv = __ldcg((const float2*)&g_u[b * ITR + n0]);
                float2 ho = __ldcg((const float2*)&hfo[b * HH + GST + n0]);
                float nh0 = uv.x * ho.x + (1.0f - uv.x) * c0;
                float nh1 = uv.y * ho.y + (1.0f - uv.y) * c1;
                *(float2*)&out[((size_t)b * TT + t) * HH + GST + n0] = make_float2(nh0, nh1);
                *(float2*)&hfn[b * HH + GST + n0] = make_float2(nh0, nh1);
                int kcol = GST + n0;
                int idx = (((nbuf * 8 + w4) * 64 + (kcol >> 4)) * 32) * 4
                          + frag_idx(b, kcol);
                g_Hh[idx] = bfpack(nh0, nh1);
                g_Hl[idx] = bfpack(bflo(nh0), bflo(nh1));
            }
        }
        sense ^= 1u; grid_barrier(sense);

        // ====== phase 3: ghost. Team of 4 splits k 8/8/8/8 ======
        {
            const uint4* Nh4 = ((const uint4*)g_Hh)
                               + ((nbuf * 8 + w4) * 64 + 32) * 32 + lane;
            const uint4* Nl4 = ((const uint4*)g_Hl)
                               + ((nbuf * 8 + w4) * 64 + 32) * 32 + lane;
            Frag3 F; f3zero(F);
            const int kb = q * 8;
            #pragma unroll 4
            for (int kt = 0; kt < 8; ++kt) {
                uint4 Ah = __ldcg(Nh4 + (kb + kt) * 32);
                uint4 Al = __ldcg(Nl4 + (kb + kt) * 32);
                uint2 bhv = Bh_h[(kb + kt) * 32 + lane];
                uint2 blv = Bh_l[(kb + kt) * 32 + lane];
                mma3(F, Ah, Al, bhv, blv);
            }
            sPart[w * 32 + lane] = make_float4(f3get(F, 0), f3get(F, 1),
                                               f3get(F, 2), f3get(F, 3));
            __syncthreads();
            if (q < 2) {
                float4 p0 = sPart[(w4 * 4 + 0) * 32 + lane];
                float4 p1 = sPart[(w4 * 4 + 1) * 32 + lane];
                float4 p2 = sPart[(w4 * 4 + 2) * 32 + lane];
                float4 p3 = sPart[(w4 * 4 + 3) * 32 + lane];
                float c0v = q ? (p0.z + p1.z + p2.z + p3.z)
                              : (p0.x + p1.x + p2.x + p3.x);
                float c1v = q ? (p0.w + p1.w + p2.w + p3.w)
                              : (p0.y + p1.y + p2.y + p3.y);
                int nl0 = 2 * (lane & 3);
                int n0  = cta * 8 + nl0;                // ghost col (even)
                float g0 = tanhf(c0v + sBh[nl0]);
                float g1 = tanhf(c1v + sBh[nl0 + 1]);
                int b = w4 * 16 + (lane >> 2) + q * 8;
                *(float2*)&out[((size_t)b * TT + t) * HH + n0] = make_float2(g0, g1);
                *(float2*)&hfn[b * HH + n0] = make_float2(g0, g1);
                int idx = (((nbuf * 8 + w4) * 64 + (n0 >> 4)) * 32) * 4 + frag_idx(b, n0);
                g_Hh[idx] = bfpack(g0, g1);
                g_Hl[idx] = bfpack(bflo(g0), bflo(g1));
            }
        }
        sense ^= 1u; grid_barrier(sense);
        // 3*512 = 1536 barriers (even): replay-safe.
    }

    // ---- h_final tail: final h lives in g_hf[0] (nbuf at t=511 is 0) ----
    if (out_size >= (int)((size_t)BB * TT * HH + (size_t)BB * HH)) {
        float* hf = out + (size_t)BB * TT * HH;
        for (int i = cta * NTHR + tid; i < BB * HH; i += NCTAS * NTHR)
            hf[i] = __ldcg(&g_hf[0][i]);
    }
}

extern "C" void kernel_launch(void* const* d_in, const int* in_sizes, int n_in,
                              void* d_out, int out_size) {
    const float* x   = (const float*)d_in[0];
    const float* hid = (const float*)d_in[1];
    const float* Wg  = (const float*)d_in[2];
    const float* Wc  = (const float*)d_in[3];
    const float* Wh  = (const float*)d_in[4];
    const float* bg  = (const float*)d_in[5];
    const float* bc  = (const float*)d_in[6];
    const float* bh  = (const float*)d_in[7];
    float* out = (float*)d_out;

    gg_pack<<<2048, 256>>>(x, hid);

    const int smem_bytes = (2 * 80 * 64 * 2 + 80 * 64 * 2 + 32 * 64 * 2) * 4
                           + 32 * 4 + 32 * 32 * 16;        // 155,776 B
    cudaFuncSetAttribute(ghostgru_tc,
                         cudaFuncAttributeMaxDynamicSharedMemorySize, smem_bytes);

    ghostgru_tc<<<NCTAS, NTHR, smem_bytes>>>(
        Wg, Wc, Wh, bg, bc, bh, out, out_size);
}

// round 17
// speedup vs baseline: 1.5126x; 1.5126x over previous
#include <cuda_runtime.h>
#include <cuda_bf16.h>
#include <math.h>

// Problem constants
#define BB    128
#define TT    512
#define FF    256
#define HH    1024
#define GST   512
#define ITR   512
#define KGC   1280      // gate/cand reduction dim

// Launch shape: 64 fat CTAs, 16 warps each (2 warps cooperate per batch mtile)
#define NCTAS 64
#define NTHR  512

// ---------------- device globals (scratch + barrier state) ----------------
__device__ unsigned g_bar_count = 0;
__device__ unsigned g_bar_sense = 0;

// Fragment-ready split-bf16 scratches. u32 = 2 bf16 (k, k+1 halves).
// X: [t][mt 8][kt 16][lane 32][reg 4]
__device__ __align__(16) unsigned g_Xh[(size_t)TT * 8 * 16 * 32 * 4];
__device__ __align__(16) unsigned g_Xl[(size_t)TT * 8 * 16 * 32 * 4];
// H ping-pong: [buf 2][mt 8][kt 64][lane][reg]   (h = [ghost | intr], k=1024)
__device__ __align__(16) unsigned g_Hh[2 * 8 * 64 * 32 * 4];
__device__ __align__(16) unsigned g_Hl[2 * 8 * 64 * 32 * 4];
// R (r*h_intr): [mt 8][kt 32][lane][reg]
__device__ __align__(16) unsigned g_Rh[8 * 32 * 32 * 4];
__device__ __align__(16) unsigned g_Rl[8 * 32 * 32 * 4];
// elementwise fp32 scratch
__device__ __align__(16) float g_u[BB * ITR];        // u gate [b][n]
__device__ __align__(16) float g_hf[2][BB * HH];     // fp32 h ping-pong

// Grid-wide sense-reversing barrier (64 CTAs, 1/SM, single wave).
// 1536 barriers/launch (even) -> sense ends 0; count wraps -> replay-safe.
__device__ __forceinline__ void grid_barrier(unsigned sense) {
    __syncthreads();
    if (threadIdx.x == 0) {
        __threadfence();
        unsigned old = atomicInc(&g_bar_count, NCTAS - 1u);
        if (old == NCTAS - 1u) {
            atomicExch(&g_bar_sense, sense);
        } else {
            while (((volatile unsigned*)&g_bar_sense)[0] != sense) { }
        }
        __threadfence();
    }
    __syncthreads();
}

// ---------------- bf16-split helpers ----------------
__device__ __forceinline__ unsigned bfpack(float v0, float v1) {
    unsigned short s0 = __bfloat16_as_ushort(__float2bfloat16(v0));
    unsigned short s1 = __bfloat16_as_ushort(__float2bfloat16(v1));
    return (unsigned)s0 | ((unsigned)s1 << 16);
}
__device__ __forceinline__ float bflo(float v) {
    return v - __bfloat162float(__float2bfloat16(v));
}

// mma.sync m16n8k16 row.col bf16 -> f32
__device__ __forceinline__ void mma_bf16(float* c, uint4 a, unsigned b0, unsigned b1) {
    asm volatile(
        "mma.sync.aligned.m16n8k16.row.col.f32.bf16.bf16.f32 "
        "{%0,%1,%2,%3},{%4,%5,%6,%7},{%8,%9},{%0,%1,%2,%3};"
        : "+f"(c[0]), "+f"(c[1]), "+f"(c[2]), "+f"(c[3])
        : "r"(a.x), "r"(a.y), "r"(a.z), "r"(a.w), "r"(b0), "r"(b1));
}

struct Frag3 { float hh[4], hl[4], lh[4]; };
__device__ __forceinline__ void f3zero(Frag3& f) {
    #pragma unroll
    for (int i = 0; i < 4; ++i) { f.hh[i] = 0.f; f.hl[i] = 0.f; f.lh[i] = 0.f; }
}
// 3-term split accumulation: C += Ah*Bh + Ah*Bl + Al*Bh (independent accs)
__device__ __forceinline__ void mma3(Frag3& f, uint4 Ah, uint4 Al, uint2 Bh, uint2 Bl) {
    mma_bf16(f.hh, Ah, Bh.x, Bh.y);
    mma_bf16(f.hl, Ah, Bl.x, Bl.y);
    mma_bf16(f.lh, Al, Bh.x, Bh.y);
}
__device__ __forceinline__ float f3get(const Frag3& f, int i) {
    return f.hh[i] + f.hl[i] + f.lh[i];
}

// A-fragment u32 index math (value pair at batch-row m, even k-col k0)
__device__ __forceinline__ int frag_idx(int m, int k0) {
    int rr = m & 15, kk = k0 & 15;
    return ((rr & 7) * 4 + ((kk & 7) >> 1)) * 4 + (rr >> 3) + ((kk >> 3) << 1);
}

// ---------------- pre-pass: split x (all t) and h0 into fragment scratch ----------------
extern "C" __global__ void gg_pack(const float* __restrict__ x,
                                   const float* __restrict__ hid) {
    const size_t nX = (size_t)TT * 8 * 16 * 32 * 4;
    for (size_t i = (size_t)blockIdx.x * blockDim.x + threadIdx.x; i < nX;
         i += (size_t)gridDim.x * blockDim.x) {
        unsigned reg = (unsigned)i & 3u;
        unsigned lane = (unsigned)(i >> 2) & 31u;
        unsigned kt = (unsigned)(i >> 7) & 15u;
        unsigned mt = (unsigned)(i >> 11) & 7u;
        unsigned t  = (unsigned)(i >> 14);
        int r  = (int)(lane >> 2) + (int)(reg & 1u) * 8;
        int k0 = (int)kt * 16 + (int)(lane & 3u) * 2 + (int)(reg >> 1) * 8;
        int b  = (int)mt * 16 + r;
        float v0 = x[((size_t)b * TT + t) * FF + k0];
        float v1 = x[((size_t)b * TT + t) * FF + k0 + 1];
        g_Xh[i] = bfpack(v0, v1);
        g_Xl[i] = bfpack(bflo(v0), bflo(v1));
    }
    const int nH = 8 * 64 * 32 * 4;     // buf 0 only
    for (int i = blockIdx.x * blockDim.x + threadIdx.x; i < nH;
         i += gridDim.x * blockDim.x) {
        int reg = i & 3, lane = (i >> 2) & 31, kt = (i >> 7) & 63, mt = (i >> 13) & 7;
        int r  = (lane >> 2) + (reg & 1) * 8;
        int k0 = kt * 16 + (lane & 3) * 2 + (reg >> 1) * 8;
        int b  = mt * 16 + r;
        float v0 = hid[b * HH + k0], v1 = hid[b * HH + k0 + 1];
        g_Hh[i] = bfpack(v0, v1);
        g_Hl[i] = bfpack(bflo(v0), bflo(v1));
    }
    for (int i = blockIdx.x * blockDim.x + threadIdx.x; i < BB * HH;
         i += gridDim.x * blockDim.x)
        g_hf[0][i] = hid[i];
}

// ---------------- persistent tensor-core kernel ----------------
extern "C" __global__ void __launch_bounds__(NTHR, 1)
ghostgru_tc(const float* __restrict__ Wg,    // (1024, 1280)
            const float* __restrict__ Wc,    // (512, 1280)
            const float* __restrict__ Wh,    // (512, 512)
            const float* __restrict__ bg,
            const float* __restrict__ bc,
            const float* __restrict__ bh,
            float*       __restrict__ out,   // (B,T,H) [+ (B,H) tail]
            int out_size)
{
    extern __shared__ unsigned smu[];
    unsigned* sWgh = smu;                  // gate B frags hi: [nt2][kt80][lane][reg2]
    unsigned* sWgl = sWgh + 2 * 80 * 64;   // 10240 each
    unsigned* sWch = sWgl + 2 * 80 * 64;   // cand: [kt80][lane][reg2] = 5120
    unsigned* sWcl = sWch + 80 * 64;
    unsigned* sWhh = sWcl + 80 * 64;       // ghost: [kt32][lane][reg2] = 2048
    unsigned* sWhl = sWhh + 32 * 64;
    float* sBg = (float*)(sWhl + 32 * 64); // 16
    float* sBc = sBg + 16;                 // 8
    float* sBh = sBc + 8;                  // 8
    float4* sPart = (float4*)(sBh + 8);    // [32 slots][32 lanes] partials = 16KB

    const int cta  = blockIdx.x;
    const int tid  = threadIdx.x;
    const int w    = tid >> 5;             // warp 0..15
    const int w2   = w >> 1;               // batch mtile 0..7
    const int half = w & 1;                // pair half
    const int lane = tid & 31;
    const bool is_r = (cta < 32);          // gate rows < 512 are r-gates

    // ---- stage split weights into SMEM in B-fragment order ----
    for (int p = tid; p < 2 * 80 * 64; p += NTHR) {
        int nt = p / (80 * 64); int rem = p % (80 * 64);
        int kt = rem >> 6; int q = rem & 63; int ln = q >> 1; int rg = q & 1;
        int nrow = cta * 16 + nt * 8 + (ln >> 2);
        int k0 = kt * 16 + (ln & 3) * 2 + rg * 8;
        float v0 = Wg[(size_t)nrow * KGC + k0];
        float v1 = Wg[(size_t)nrow * KGC + k0 + 1];
        sWgh[p] = bfpack(v0, v1);
        sWgl[p] = bfpack(bflo(v0), bflo(v1));
    }
    for (int p = tid; p < 80 * 64; p += NTHR) {
        int kt = p >> 6; int q = p & 63; int ln = q >> 1; int rg = q & 1;
        int nrow = cta * 8 + (ln >> 2);
        int k0 = kt * 16 + (ln & 3) * 2 + rg * 8;
        float v0 = Wc[(size_t)nrow * KGC + k0];
        float v1 = Wc[(size_t)nrow * KGC + k0 + 1];
        sWch[p] = bfpack(v0, v1);
        sWcl[p] = bfpack(bflo(v0), bflo(v1));
    }
    for (int p = tid; p < 32 * 64; p += NTHR) {
        int kt = p >> 6; int q = p & 63; int ln = q >> 1; int rg = q & 1;
        int nrow = cta * 8 + (ln >> 2);
        int k0 = kt * 16 + (ln & 3) * 2 + rg * 8;
        float v0 = Wh[(size_t)nrow * ITR + k0];
        float v1 = Wh[(size_t)nrow * ITR + k0 + 1];
        sWhh[p] = bfpack(v0, v1);
        sWhl[p] = bfpack(bflo(v0), bflo(v1));
    }
    if (tid < 16) sBg[tid] = bg[cta * 16 + tid];
    if (tid < 8)  sBc[tid] = bc[cta * 8 + tid];
    if (tid < 8)  sBh[tid] = bh[cta * 8 + tid];
    __syncthreads();

    const uint2* Bg_h = (const uint2*)sWgh;   // index (nt*80+kt)*32 + lane
    const uint2* Bg_l = (const uint2*)sWgl;
    const uint2* Bc_h = (const uint2*)sWch;   // index kt*32 + lane
    const uint2* Bc_l = (const uint2*)sWcl;
    const uint2* Bh_h = (const uint2*)sWhh;
    const uint2* Bh_l = (const uint2*)sWhl;

    unsigned sense = 0;

    for (int t = 0; t < TT; ++t) {
        const int buf = t & 1, nbuf = (t + 1) & 1;
        const float* hfo = g_hf[buf];
        float*       hfn = g_hf[nbuf];

        const uint4* Xh4 = ((const uint4*)g_Xh) + (((size_t)t * 8 + w2) * 16) * 32 + lane;
        const uint4* Xl4 = ((const uint4*)g_Xl) + (((size_t)t * 8 + w2) * 16) * 32 + lane;
        const uint4* Hh4 = ((const uint4*)g_Hh) + ((buf * 8 + w2) * 64) * 32 + lane;
        const uint4* Hl4 = ((const uint4*)g_Hl) + ((buf * 8 + w2) * 64) * 32 + lane;
        const uint4* Rh4 = ((const uint4*)g_Rh) + (w2 * 32) * 32 + lane;
        const uint4* Rl4 = ((const uint4*)g_Rl) + (w2 * 32) * 32 + lane;

        // ====== phase 1: gate. Warp pair splits K (40/40); each warp does BOTH
        // n-tiles per kt (A-loads shared), then SMEM-reduces the pair's partials. ======
        {
            Frag3 F0, F1; f3zero(F0); f3zero(F1);
            if (half == 0) {
                #pragma unroll 4
                for (int kt = 0; kt < 16; ++kt) {       // x: logical kt 0..15
                    uint4 Ah = __ldg(Xh4 + kt * 32);
                    uint4 Al = __ldg(Xl4 + kt * 32);
                    uint2 b0h = Bg_h[kt * 32 + lane],        b0l = Bg_l[kt * 32 + lane];
                    uint2 b1h = Bg_h[(80 + kt) * 32 + lane], b1l = Bg_l[(80 + kt) * 32 + lane];
                    mma3(F0, Ah, Al, b0h, b0l);
                    mma3(F1, Ah, Al, b1h, b1l);
                }
                #pragma unroll 4
                for (int kt = 0; kt < 24; ++kt) {       // h: logical kt 16..39
                    uint4 Ah = __ldcg(Hh4 + kt * 32);
                    uint4 Al = __ldcg(Hl4 + kt * 32);
                    int kg = 16 + kt;
                    uint2 b0h = Bg_h[kg * 32 + lane],        b0l = Bg_l[kg * 32 + lane];
                    uint2 b1h = Bg_h[(80 + kg) * 32 + lane], b1l = Bg_l[(80 + kg) * 32 + lane];
                    mma3(F0, Ah, Al, b0h, b0l);
                    mma3(F1, Ah, Al, b1h, b1l);
                }
            } else {
                #pragma unroll 4
                for (int kt = 24; kt < 64; ++kt) {      // h: logical kt 40..79
                    uint4 Ah = __ldcg(Hh4 + kt * 32);
                    uint4 Al = __ldcg(Hl4 + kt * 32);
                    int kg = 16 + kt;
                    uint2 b0h = Bg_h[kg * 32 + lane],        b0l = Bg_l[kg * 32 + lane];
                    uint2 b1h = Bg_h[(80 + kg) * 32 + lane], b1l = Bg_l[(80 + kg) * 32 + lane];
                    mma3(F0, Ah, Al, b0h, b0l);
                    mma3(F1, Ah, Al, b1h, b1l);
                }
            }
            // partials: slot (w*2 + nt)
            sPart[(w * 2 + 0) * 32 + lane] = make_float4(f3get(F0, 0), f3get(F0, 1),
                                                         f3get(F0, 2), f3get(F0, 3));
            sPart[(w * 2 + 1) * 32 + lane] = make_float4(f3get(F1, 0), f3get(F1, 1),
                                                         f3get(F1, 2), f3get(F1, 3));
            __syncthreads();
            // this warp finishes ntile = half
            float4 pa = sPart[((w2 * 2 + 0) * 2 + half) * 32 + lane];
            float4 pb = sPart[((w2 * 2 + 1) * 2 + half) * 32 + lane];
            float c0 = pa.x + pb.x, c1 = pa.y + pb.y;
            float c2 = pa.z + pb.z, c3 = pa.w + pb.w;
            int nl0 = half * 8 + 2 * (lane & 3);
            int ng0 = cta * 16 + nl0;                   // gate row (even)
            float bia0 = sBg[nl0], bia1 = sBg[nl0 + 1];
            #pragma unroll
            for (int rh = 0; rh < 2; ++rh) {
                int b = w2 * 16 + (lane >> 2) + rh * 8;
                float z0 = (rh ? c2 : c0) + bia0;
                float z1 = (rh ? c3 : c1) + bia1;
                float s0 = 1.0f / (1.0f + __expf(-z0));
                float s1 = 1.0f / (1.0f + __expf(-z1));
                if (is_r) {
                    float2 ho = __ldcg((const float2*)&hfo[b * HH + GST + ng0]);
                    float r0 = s0 * ho.x, r1 = s1 * ho.y;
                    int idx = ((w2 * 32 + (ng0 >> 4)) * 32) * 4 + frag_idx(b, ng0);
                    g_Rh[idx] = bfpack(r0, r1);
                    g_Rl[idx] = bfpack(bflo(r0), bflo(r1));
                } else {
                    *(float2*)&g_u[b * ITR + (ng0 - GST)] = make_float2(s0, s1);
                }
            }
        }
        sense ^= 1u; grid_barrier(sense);

        // ============ phase 2: cand. Warp pair splits k (40/40 ktiles). ============
        {
            Frag3 F; f3zero(F);
            if (half == 0) {
                #pragma unroll 4
                for (int kt = 0; kt < 16; ++kt) {       // x: logical kt 0..15
                    uint4 Ah = __ldg(Xh4 + kt * 32);
                    uint4 Al = __ldg(Xl4 + kt * 32);
                    uint2 bhv = Bc_h[kt * 32 + lane], blv = Bc_l[kt * 32 + lane];
                    mma3(F, Ah, Al, bhv, blv);
                }
                #pragma unroll 4
                for (int kt = 0; kt < 24; ++kt) {       // ghost: logical 16..39
                    uint4 Ah = __ldcg(Hh4 + kt * 32);
                    uint4 Al = __ldcg(Hl4 + kt * 32);
                    uint2 bhv = Bc_h[(16 + kt) * 32 + lane];
                    uint2 blv = Bc_l[(16 + kt) * 32 + lane];
                    mma3(F, Ah, Al, bhv, blv);
                }
            } else {
                #pragma unroll 4
                for (int kt = 24; kt < 32; ++kt) {      // ghost: logical 40..47
                    uint4 Ah = __ldcg(Hh4 + kt * 32);
                    uint4 Al = __ldcg(Hl4 + kt * 32);
                    uint2 bhv = Bc_h[(16 + kt) * 32 + lane];
                    uint2 blv = Bc_l[(16 + kt) * 32 + lane];
                    mma3(F, Ah, Al, bhv, blv);
                }
                #pragma unroll 4
                for (int kt = 0; kt < 32; ++kt) {       // r_state: logical 48..79
                    uint4 Ah = __ldcg(Rh4 + kt * 32);
                    uint4 Al = __ldcg(Rl4 + kt * 32);
                    uint2 bhv = Bc_h[(48 + kt) * 32 + lane];
                    uint2 blv = Bc_l[(48 + kt) * 32 + lane];
                    mma3(F, Ah, Al, bhv, blv);
                }
            }
            // cross-warp-pair reduction via SMEM
            sPart[w * 32 + lane] = make_float4(f3get(F, 0), f3get(F, 1),
                                               f3get(F, 2), f3get(F, 3));
            __syncthreads();
            float4 pa = sPart[(w2 * 2 + 0) * 32 + lane];
            float4 pb = sPart[(w2 * 2 + 1) * 32 + lane];
            // this warp handles row-half rh = half
            float c0v = half ? (pa.z + pb.z) : (pa.x + pb.x);
            float c1v = half ? (pa.w + pb.w) : (pa.y + pb.y);
            int nl0 = 2 * (lane & 3);
            int n0  = cta * 8 + nl0;                    // intr col (even)
            float c0 = tanhf(c0v + sBc[nl0]);
            float c1 = tanhf(c1v + sBc[nl0 + 1]);
            int b = w2 * 16 + (lane >> 2) + half * 8;
            float2 uv = __ldcg((const float2*)&g_u[b * ITR + n0]);
            float2 ho = __ldcg((const float2*)&hfo[b * HH + GST + n0]);
            float nh0 = uv.x * ho.x + (1.0f - uv.x) * c0;
            float nh1 = uv.y * ho.y + (1.0f - uv.y) * c1;
            *(float2*)&out[((size_t)b * TT + t) * HH + GST + n0] = make_float2(nh0, nh1);
            *(float2*)&hfn[b * HH + GST + n0] = make_float2(nh0, nh1);
            int kcol = GST + n0;
            int idx = (((nbuf * 8 + w2) * 64 + (kcol >> 4)) * 32) * 4 + frag_idx(b, kcol);
            g_Hh[idx] = bfpack(nh0, nh1);
            g_Hl[idx] = bfpack(bflo(nh0), bflo(nh1));
        }
        sense ^= 1u; grid_barrier(sense);

        // ============ phase 3: ghost. Warp pair splits k (16/16 ktiles). ============
        {
            const uint4* Nh4 = ((const uint4*)g_Hh)
                               + ((nbuf * 8 + w2) * 64 + 32 + half * 16) * 32 + lane;
            const uint4* Nl4 = ((const uint4*)g_Hl)
                               + ((nbuf * 8 + w2) * 64 + 32 + half * 16) * 32 + lane;
            Frag3 F; f3zero(F);
            #pragma unroll 4
            for (int kt = 0; kt < 16; ++kt) {
                uint4 Ah = __ldcg(Nh4 + kt * 32);
                uint4 Al = __ldcg(Nl4 + kt * 32);
                uint2 bhv = Bh_h[(half * 16 + kt) * 32 + lane];
                uint2 blv = Bh_l[(half * 16 + kt) * 32 + lane];
                mma3(F, Ah, Al, bhv, blv);
            }
            sPart[w * 32 + lane] = make_float4(f3get(F, 0), f3get(F, 1),
                                               f3get(F, 2), f3get(F, 3));
            __syncthreads();
            float4 pa = sPart[(w2 * 2 + 0) * 32 + lane];
            float4 pb = sPart[(w2 * 2 + 1) * 32 + lane];
            float c0v = half ? (pa.z + pb.z) : (pa.x + pb.x);
            float c1v = half ? (pa.w + pb.w) : (pa.y + pb.y);
            int nl0 = 2 * (lane & 3);
            int n0  = cta * 8 + nl0;                    // ghost col (even)
            float g0 = tanhf(c0v + sBh[nl0]);
            float g1 = tanhf(c1v + sBh[nl0 + 1]);
            int b = w2 * 16 + (lane >> 2) + half * 8;
            *(float2*)&out[((size_t)b * TT + t) * HH + n0] = make_float2(g0, g1);
            *(float2*)&hfn[b * HH + n0] = make_float2(g0, g1);
            int idx = (((nbuf * 8 + w2) * 64 + (n0 >> 4)) * 32) * 4 + frag_idx(b, n0);
            g_Hh[idx] = bfpack(g0, g1);
            g_Hl[idx] = bfpack(bflo(g0), bflo(g1));
        }
        sense ^= 1u; grid_barrier(sense);
        // 3*512 = 1536 barriers (even): replay-safe.
    }

    // ---- h_final tail: final h lives in g_hf[0] (nbuf at t=511 is 0) ----
    if (out_size >= (int)((size_t)BB * TT * HH + (size_t)BB * HH)) {
        float* hf = out + (size_t)BB * TT * HH;
        for (int i = cta * NTHR + tid; i < BB * HH; i += NCTAS * NTHR)
            hf[i] = __ldcg(&g_hf[0][i]);
    }
}

extern "C" void kernel_launch(void* const* d_in, const int* in_sizes, int n_in,
                              void* d_out, int out_size) {
    const float* x   = (const float*)d_in[0];
    const float* hid = (const float*)d_in[1];
    const float* Wg  = (const float*)d_in[2];
    const float* Wc  = (const float*)d_in[3];
    const float* Wh  = (const float*)d_in[4];
    const float* bg  = (const float*)d_in[5];
    const float* bc  = (const float*)d_in[6];
    const float* bh  = (const float*)d_in[7];
    float* out = (float*)d_out;

    gg_pack<<<2048, 256>>>(x, hid);

    const int smem_bytes = (2 * 80 * 64 * 2 + 80 * 64 * 2 + 32 * 64 * 2) * 4
                           + 32 * 4 + 32 * 32 * 16;        // 155,776 B
    cudaFuncSetAttribute(ghostgru_tc,
                         cudaFuncAttributeMaxDynamicSharedMemorySize, smem_bytes);

    ghostgru_tc<<<NCTAS, NTHR, smem_bytes>>>(
        Wg, Wc, Wh, bg, bc, bh, out, out_size);
}